// round 1
// baseline (speedup 1.0000x reference)
#include <cuda_runtime.h>
#include <math.h>

// Problem shape (AdaptiveSemanticFilter_15126874816924)
#define BB 256
#define LL1 512
#define LL2 256
#define DD 256

static const int BM = 64, BN = 64, BK = 16;

// Scratch: 128 MiB sim buffer + norms + stats (device globals: allocation-free)
__device__ float  g_sim[(size_t)BB * LL1 * LL2];
__device__ float  g_norm_v[BB * LL1];
__device__ float  g_norm_t[BB * LL2];
__device__ double g_sum;
__device__ double g_sumsq;
__device__ float  g_thresh;

// ---------------------------------------------------------------------------
// Kernel 1: row L2-norms for V and T; also zero the stats accumulators.
// One warp per row of length D=256.
// ---------------------------------------------------------------------------
__global__ void norm_kernel(const float* __restrict__ V, const float* __restrict__ T) {
    if (blockIdx.x == 0 && threadIdx.x == 0) { g_sum = 0.0; g_sumsq = 0.0; }

    int gwarp = (blockIdx.x * blockDim.x + threadIdx.x) >> 5;
    int lane  = threadIdx.x & 31;
    const int n_v = BB * LL1;
    const int n_t = BB * LL2;
    if (gwarp >= n_v + n_t) return;

    const float* row;
    float* dst;
    if (gwarp < n_v) {
        row = V + (size_t)gwarp * DD;
        dst = &g_norm_v[gwarp];
    } else {
        int r = gwarp - n_v;
        row = T + (size_t)r * DD;
        dst = &g_norm_t[r];
    }

    float ss = 0.0f;
    const float4* r4 = (const float4*)row;
    #pragma unroll
    for (int j = lane; j < DD / 4; j += 32) {
        float4 v = r4[j];
        ss += v.x * v.x + v.y * v.y + v.z * v.z + v.w * v.w;
    }
    #pragma unroll
    for (int off = 16; off > 0; off >>= 1)
        ss += __shfl_down_sync(0xffffffffu, ss, off);
    if (lane == 0) *dst = sqrtf(ss);
}

// ---------------------------------------------------------------------------
// Kernel 2: batched GEMM sim[b,l,m] = dot(V[b,l,:], T[b,m,:]) / (nv*nt + eps)
// BM=BN=64, BK=16, 256 threads, 4x4 micro-tile per thread.
// Fused epilogue: store sim to scratch + accumulate global sum / sumsq (double).
// ---------------------------------------------------------------------------
__global__ __launch_bounds__(256) void gemm_sim_kernel(const float* __restrict__ V,
                                                       const float* __restrict__ T) {
    __shared__ float As[BK][BM + 4];
    __shared__ float Bs[BK][BN + 4];

    const int b  = blockIdx.z;
    const int m0 = blockIdx.y * BM;   // along L1
    const int n0 = blockIdx.x * BN;   // along L2

    const int tid = threadIdx.x;      // 0..255
    const int tx  = tid & 15;         // 0..15 -> n micro
    const int ty  = tid >> 4;         // 0..15 -> m micro

    const float* Vb = V + (size_t)b * LL1 * DD;
    const float* Tb = T + (size_t)b * LL2 * DD;

    // loader mapping: each thread loads one float4 of A tile and one of B tile
    const int lr = tid >> 2;          // 0..63 tile row
    const int lk = (tid & 3) * 4;     // k sub-offset 0,4,8,12

    float acc[4][4] = {};

    for (int k0 = 0; k0 < DD; k0 += BK) {
        float4 av = *(const float4*)&Vb[(size_t)(m0 + lr) * DD + k0 + lk];
        float4 bv = *(const float4*)&Tb[(size_t)(n0 + lr) * DD + k0 + lk];
        __syncthreads();
        As[lk + 0][lr] = av.x; As[lk + 1][lr] = av.y;
        As[lk + 2][lr] = av.z; As[lk + 3][lr] = av.w;
        Bs[lk + 0][lr] = bv.x; Bs[lk + 1][lr] = bv.y;
        Bs[lk + 2][lr] = bv.z; Bs[lk + 3][lr] = bv.w;
        __syncthreads();

        #pragma unroll
        for (int k = 0; k < BK; k++) {
            float4 a4 = *(const float4*)&As[k][ty * 4];
            float4 b4 = *(const float4*)&Bs[k][tx * 4];
            acc[0][0] += a4.x * b4.x; acc[0][1] += a4.x * b4.y;
            acc[0][2] += a4.x * b4.z; acc[0][3] += a4.x * b4.w;
            acc[1][0] += a4.y * b4.x; acc[1][1] += a4.y * b4.y;
            acc[1][2] += a4.y * b4.z; acc[1][3] += a4.y * b4.w;
            acc[2][0] += a4.z * b4.x; acc[2][1] += a4.z * b4.y;
            acc[2][2] += a4.z * b4.z; acc[2][3] += a4.z * b4.w;
            acc[3][0] += a4.w * b4.x; acc[3][1] += a4.w * b4.y;
            acc[3][2] += a4.w * b4.z; acc[3][3] += a4.w * b4.w;
        }
    }

    // epilogue: normalize, store sim, accumulate stats
    float nv[4], nt[4];
    #pragma unroll
    for (int i = 0; i < 4; i++) nv[i] = g_norm_v[b * LL1 + m0 + ty * 4 + i];
    #pragma unroll
    for (int j = 0; j < 4; j++) nt[j] = g_norm_t[b * LL2 + n0 + tx * 4 + j];

    double lsum = 0.0, lsq = 0.0;
    #pragma unroll
    for (int i = 0; i < 4; i++) {
        float4 r;
        float s0 = acc[i][0] / (nv[i] * nt[0] + 1e-9f);
        float s1 = acc[i][1] / (nv[i] * nt[1] + 1e-9f);
        float s2 = acc[i][2] / (nv[i] * nt[2] + 1e-9f);
        float s3 = acc[i][3] / (nv[i] * nt[3] + 1e-9f);
        r.x = s0; r.y = s1; r.z = s2; r.w = s3;
        lsum += (double)s0 + (double)s1 + (double)s2 + (double)s3;
        lsq  += (double)s0 * s0 + (double)s1 * s1 +
                (double)s2 * s2 + (double)s3 * s3;
        size_t row = (size_t)(b * LL1 + m0 + ty * 4 + i);
        *(float4*)&g_sim[row * LL2 + n0 + tx * 4] = r;
    }

    // block reduce doubles -> 2 atomics per block
    #pragma unroll
    for (int off = 16; off > 0; off >>= 1) {
        lsum += __shfl_down_sync(0xffffffffu, lsum, off);
        lsq  += __shfl_down_sync(0xffffffffu, lsq,  off);
    }
    __shared__ double ws[8], wq[8];
    int wid = tid >> 5, lane = tid & 31;
    if (lane == 0) { ws[wid] = lsum; wq[wid] = lsq; }
    __syncthreads();
    if (tid == 0) {
        double s = 0.0, q = 0.0;
        #pragma unroll
        for (int w = 0; w < 8; w++) { s += ws[w]; q += wq[w]; }
        atomicAdd(&g_sum, s);
        atomicAdd(&g_sumsq, q);
    }
}

// ---------------------------------------------------------------------------
// Kernel 3: threshold b2 = mu2 + sigma2 * sqrt(-2*ln(Z2+eps))   (L1 != L2 path)
// ---------------------------------------------------------------------------
__global__ void thresh_kernel() {
    const double n  = (double)BB * LL1 * LL2;
    double mu  = g_sum / n;
    double var = (g_sumsq - g_sum * g_sum / n) / (n - 1.0);
    double sigma = sqrt(fmax(var, 0.0));
    float z = sqrtf(-2.0f * logf(0.2f + 1e-9f));
    g_thresh = (float)mu + (float)sigma * z;
}

// ---------------------------------------------------------------------------
// Kernel 4: out = sim * (mask + eps); in fp32: mask=1 -> factor==1.0f exactly,
// mask=0 -> factor==1e-9f.
// ---------------------------------------------------------------------------
__global__ void finalize_kernel(float* __restrict__ out) {
    const float thr = g_thresh;
    size_t i = (size_t)blockIdx.x * blockDim.x + threadIdx.x;
    const size_t n4 = (size_t)BB * LL1 * LL2 / 4;
    if (i >= n4) return;
    float4 s = ((const float4*)g_sim)[i];
    float4 r;
    r.x = (s.x > thr) ? s.x : s.x * 1e-9f;
    r.y = (s.y > thr) ? s.y : s.y * 1e-9f;
    r.z = (s.z > thr) ? s.z : s.z * 1e-9f;
    r.w = (s.w > thr) ? s.w : s.w * 1e-9f;
    ((float4*)out)[i] = r;
}

// ---------------------------------------------------------------------------
extern "C" void kernel_launch(void* const* d_in, const int* in_sizes, int n_in,
                              void* d_out, int out_size) {
    const float* V = (const float*)d_in[0];   // visual_units  [B,L1,D]
    const float* T = (const float*)d_in[1];   // textual_units [B,L2,D]
    float* out = (float*)d_out;               // [B,L1,L2]

    // norms: one warp per row, (B*L1 + B*L2) rows
    int nrows = BB * LL1 + BB * LL2;
    int nblk  = (nrows * 32 + 255) / 256;
    norm_kernel<<<nblk, 256>>>(V, T);

    dim3 g(LL2 / BN, LL1 / BM, BB);
    gemm_sim_kernel<<<g, 256>>>(V, T);

    thresh_kernel<<<1, 1>>>();

    size_t n4 = (size_t)BB * LL1 * LL2 / 4;
    finalize_kernel<<<(unsigned)((n4 + 255) / 256), 256>>>(out);
}

// round 2
// speedup vs baseline: 1.2264x; 1.2264x over previous
#include <cuda_runtime.h>
#include <math.h>

// Problem shape (AdaptiveSemanticFilter_15126874816924)
#define BB 256
#define LL1 512
#define LL2 256
#define DD 256

// GEMM tiles
#define BM 128
#define BN 64
#define BK 16

// Scratch (device globals: allocation-free)
__device__ float  g_sim[(size_t)BB * LL1 * LL2];
__device__ float  g_norm_v[BB * LL1];
__device__ float  g_norm_t[BB * LL2];
__device__ double g_sum;
__device__ double g_sumsq;
__device__ float  g_thresh;

// Packed dual-fp32 FMA (sm_100a/103a). Bit-exact: two IEEE fp32 FMAs per instr.
__device__ __forceinline__ float2 ffma2(float2 a, float2 b, float2 c) {
    float2 d;
    asm("fma.rn.f32x2 %0, %1, %2, %3;"
        : "=l"(reinterpret_cast<unsigned long long&>(d))
        : "l"(reinterpret_cast<const unsigned long long&>(a)),
          "l"(reinterpret_cast<const unsigned long long&>(b)),
          "l"(reinterpret_cast<const unsigned long long&>(c)));
    return d;
}

// ---------------------------------------------------------------------------
// Kernel 1: row L2-norms for V and T; zero stats accumulators.
// ---------------------------------------------------------------------------
__global__ void norm_kernel(const float* __restrict__ V, const float* __restrict__ T) {
    if (blockIdx.x == 0 && threadIdx.x == 0) { g_sum = 0.0; g_sumsq = 0.0; }

    int gwarp = (blockIdx.x * blockDim.x + threadIdx.x) >> 5;
    int lane  = threadIdx.x & 31;
    const int n_v = BB * LL1;
    const int n_t = BB * LL2;
    if (gwarp >= n_v + n_t) return;

    const float* row;
    float* dst;
    if (gwarp < n_v) {
        row = V + (size_t)gwarp * DD;
        dst = &g_norm_v[gwarp];
    } else {
        int r = gwarp - n_v;
        row = T + (size_t)r * DD;
        dst = &g_norm_t[r];
    }

    float ss = 0.0f;
    const float4* r4 = (const float4*)row;
    #pragma unroll
    for (int j = lane; j < DD / 4; j += 32) {
        float4 v = r4[j];
        ss += v.x * v.x + v.y * v.y + v.z * v.z + v.w * v.w;
    }
    #pragma unroll
    for (int off = 16; off > 0; off >>= 1)
        ss += __shfl_down_sync(0xffffffffu, ss, off);
    if (lane == 0) *dst = sqrtf(ss);
}

// ---------------------------------------------------------------------------
// Kernel 2: batched GEMM with packed f32x2 FMAs.
// BM=128, BN=64, BK=16, 256 threads, 8x4 micro-tile per thread
// (accumulators paired along m -> 16 FFMA2 per k-step per thread).
// Fused epilogue: normalize, store sim, accumulate global sum/sumsq (double).
// ---------------------------------------------------------------------------
__global__ __launch_bounds__(256) void gemm_sim_kernel(const float* __restrict__ V,
                                                       const float* __restrict__ T) {
    __shared__ float As[BK][BM + 4];
    __shared__ float Bs[BK][BN + 4];

    const int b  = blockIdx.z;
    const int m0 = blockIdx.y * BM;   // along L1
    const int n0 = blockIdx.x * BN;   // along L2

    const int tid = threadIdx.x;      // 0..255
    const int tx  = tid & 15;         // 0..15 -> n micro (4 cols)
    const int ty  = tid >> 4;         // 0..15 -> m micro (8 rows)

    const float* Vb = V + (size_t)b * LL1 * DD;
    const float* Tb = T + (size_t)b * LL2 * DD;

    // loaders: A tile 128x16 = 512 float4 -> 2 per thread; B tile 64x16 -> 1.
    const int lr = tid >> 2;          // 0..63
    const int lk = (tid & 3) * 4;     // 0,4,8,12

    // acc[p][j]: p in 0..3 = m-pair (rows ty*8+2p, +1), j = n col
    float2 acc[4][4];
    #pragma unroll
    for (int p = 0; p < 4; p++)
        #pragma unroll
        for (int j = 0; j < 4; j++) acc[p][j] = make_float2(0.0f, 0.0f);

    for (int k0 = 0; k0 < DD; k0 += BK) {
        float4 av0 = *(const float4*)&Vb[(size_t)(m0 + lr)      * DD + k0 + lk];
        float4 av1 = *(const float4*)&Vb[(size_t)(m0 + lr + 64) * DD + k0 + lk];
        float4 bv  = *(const float4*)&Tb[(size_t)(n0 + lr)      * DD + k0 + lk];
        __syncthreads();
        As[lk + 0][lr] = av0.x; As[lk + 1][lr] = av0.y;
        As[lk + 2][lr] = av0.z; As[lk + 3][lr] = av0.w;
        As[lk + 0][lr + 64] = av1.x; As[lk + 1][lr + 64] = av1.y;
        As[lk + 2][lr + 64] = av1.z; As[lk + 3][lr + 64] = av1.w;
        Bs[lk + 0][lr] = bv.x; Bs[lk + 1][lr] = bv.y;
        Bs[lk + 2][lr] = bv.z; Bs[lk + 3][lr] = bv.w;
        __syncthreads();

        #pragma unroll
        for (int k = 0; k < BK; k++) {
            float4 a0 = *(const float4*)&As[k][ty * 8];
            float4 a1 = *(const float4*)&As[k][ty * 8 + 4];
            float4 b4 = *(const float4*)&Bs[k][tx * 4];

            float2 ap[4];
            ap[0] = make_float2(a0.x, a0.y);
            ap[1] = make_float2(a0.z, a0.w);
            ap[2] = make_float2(a1.x, a1.y);
            ap[3] = make_float2(a1.z, a1.w);

            float2 bd[4];
            bd[0] = make_float2(b4.x, b4.x);
            bd[1] = make_float2(b4.y, b4.y);
            bd[2] = make_float2(b4.z, b4.z);
            bd[3] = make_float2(b4.w, b4.w);

            #pragma unroll
            for (int p = 0; p < 4; p++)
                #pragma unroll
                for (int j = 0; j < 4; j++)
                    acc[p][j] = ffma2(ap[p], bd[j], acc[p][j]);
        }
    }

    // epilogue: normalize, store sim, accumulate stats
    float nv[8], nt[4];
    #pragma unroll
    for (int i = 0; i < 8; i++) nv[i] = g_norm_v[b * LL1 + m0 + ty * 8 + i];
    #pragma unroll
    for (int j = 0; j < 4; j++) nt[j] = g_norm_t[b * LL2 + n0 + tx * 4 + j];

    double lsum = 0.0, lsq = 0.0;
    #pragma unroll
    for (int r = 0; r < 8; r++) {
        int p = r >> 1;
        bool hi = (r & 1);
        float4 o;
        float d0 = hi ? acc[p][0].y : acc[p][0].x;
        float d1 = hi ? acc[p][1].y : acc[p][1].x;
        float d2 = hi ? acc[p][2].y : acc[p][2].x;
        float d3 = hi ? acc[p][3].y : acc[p][3].x;
        float s0 = d0 / (nv[r] * nt[0] + 1e-9f);
        float s1 = d1 / (nv[r] * nt[1] + 1e-9f);
        float s2 = d2 / (nv[r] * nt[2] + 1e-9f);
        float s3 = d3 / (nv[r] * nt[3] + 1e-9f);
        o.x = s0; o.y = s1; o.z = s2; o.w = s3;
        lsum += (double)s0 + (double)s1 + (double)s2 + (double)s3;
        lsq  += (double)s0 * s0 + (double)s1 * s1 +
                (double)s2 * s2 + (double)s3 * s3;
        size_t row = (size_t)(b * LL1 + m0 + ty * 8 + r);
        *(float4*)&g_sim[row * LL2 + n0 + tx * 4] = o;
    }

    // block reduce -> 2 atomics per block
    #pragma unroll
    for (int off = 16; off > 0; off >>= 1) {
        lsum += __shfl_down_sync(0xffffffffu, lsum, off);
        lsq  += __shfl_down_sync(0xffffffffu, lsq,  off);
    }
    __shared__ double ws[8], wq[8];
    int wid = tid >> 5, lane = tid & 31;
    if (lane == 0) { ws[wid] = lsum; wq[wid] = lsq; }
    __syncthreads();
    if (tid == 0) {
        double s = 0.0, q = 0.0;
        #pragma unroll
        for (int w = 0; w < 8; w++) { s += ws[w]; q += wq[w]; }
        atomicAdd(&g_sum, s);
        atomicAdd(&g_sumsq, q);
    }
}

// ---------------------------------------------------------------------------
// Kernel 3: threshold b2 = mu2 + sigma2 * sqrt(-2*ln(Z2+eps))  (L1 != L2 path)
// ---------------------------------------------------------------------------
__global__ void thresh_kernel() {
    const double n  = (double)BB * LL1 * LL2;
    double mu  = g_sum / n;
    double var = (g_sumsq - g_sum * g_sum / n) / (n - 1.0);
    double sigma = sqrt(fmax(var, 0.0));
    float z = sqrtf(-2.0f * logf(0.2f + 1e-9f));
    g_thresh = (float)mu + (float)sigma * z;
}

// ---------------------------------------------------------------------------
// Kernel 4: out = sim where sim > thr, else sim * 1e-9 (mask+eps in fp32).
// ---------------------------------------------------------------------------
__global__ void finalize_kernel(float* __restrict__ out) {
    const float thr = g_thresh;
    size_t i = (size_t)blockIdx.x * blockDim.x + threadIdx.x;
    const size_t n4 = (size_t)BB * LL1 * LL2 / 4;
    if (i >= n4) return;
    float4 s = ((const float4*)g_sim)[i];
    float4 r;
    r.x = (s.x > thr) ? s.x : s.x * 1e-9f;
    r.y = (s.y > thr) ? s.y : s.y * 1e-9f;
    r.z = (s.z > thr) ? s.z : s.z * 1e-9f;
    r.w = (s.w > thr) ? s.w : s.w * 1e-9f;
    ((float4*)out)[i] = r;
}

// ---------------------------------------------------------------------------
extern "C" void kernel_launch(void* const* d_in, const int* in_sizes, int n_in,
                              void* d_out, int out_size) {
    const float* V = (const float*)d_in[0];   // visual_units  [B,L1,D]
    const float* T = (const float*)d_in[1];   // textual_units [B,L2,D]
    float* out = (float*)d_out;               // [B,L1,L2]

    int nrows = BB * LL1 + BB * LL2;
    int nblk  = (nrows * 32 + 255) / 256;
    norm_kernel<<<nblk, 256>>>(V, T);

    dim3 g(LL2 / BN, LL1 / BM, BB);
    gemm_sim_kernel<<<g, 256>>>(V, T);

    thresh_kernel<<<1, 1>>>();

    size_t n4 = (size_t)BB * LL1 * LL2 / 4;
    finalize_kernel<<<(unsigned)((n4 + 255) / 256), 256>>>(out);
}